// round 6
// baseline (speedup 1.0000x reference)
#include <cuda_runtime.h>
#include <cuda_bf16.h>
#include <cstdint>

constexpr int B = 32;
constexpr int A = 16384;
constexpr int C = 81;

constexpr int APB  = 32;            // anchors per block
constexpr int FPB  = APB * C;       // 2592 floats
constexpr int V4PB = FPB / 4;       // 648 float4
constexpr int WPB  = A / 32;        // 512 mask words per batch
constexpr int BPB  = A / APB;       // 512 blocks per batch

// Scratch (device globals; no allocations allowed).
__device__ float    g_maxce[B * A];         // slow path only
__device__ unsigned g_posmask[B * WPB];     // bit: depth > 0
__device__ unsigned g_zeromask[B * WPB];    // bit: v == 0
__device__ int      g_done[B];              // ticket counters (self-resetting)

// ---------------------------------------------------------------------------
__device__ __forceinline__ float bce(float x, float t) {
    return fmaxf(x, 0.0f) + log1pf(__expf(-fabsf(x))) - t * x;
}
__device__ __forceinline__ float4 bce4(float4 x, float4 t) {
    float4 r;
    r.x = bce(x.x, t.x); r.y = bce(x.y, t.y);
    r.z = bce(x.z, t.z); r.w = bce(x.w, t.w);
    return r;
}

// ---------------------------------------------------------------------------
// Single fused kernel: BCE + per-anchor max + bitmasks; the last block of each
// batch (atomic ticket) performs the hard-negative selection + row zeroing.
// ---------------------------------------------------------------------------
__global__ void __launch_bounds__(256) fused_kernel(
    const float* __restrict__ pred,
    const float* __restrict__ tgt,
    const int*   __restrict__ depth,
    const int*   __restrict__ npr_ptr,
    float*       __restrict__ out)
{
    __shared__ float s_ce[FPB];
    __shared__ float s_m[APB];
    __shared__ int   s_scan[8];
    __shared__ unsigned long long s_red[8];
    __shared__ int   s_bc;
    __shared__ int   s_flag;

    const int tid  = threadIdx.x;
    const int lane = tid & 31;
    const int wid  = tid >> 5;
    const unsigned FULL = 0xffffffffu;
    const int batch = blockIdx.x >> 9;          // / BPB

    // ===================== Phase 1: streaming BCE =====================
    {
        const size_t base4 = (size_t)blockIdx.x * V4PB;
        const float4* __restrict__ p4 = reinterpret_cast<const float4*>(pred) + base4;
        const float4* __restrict__ t4 = reinterpret_cast<const float4*>(tgt)  + base4;
        float4* __restrict__ o4 = reinterpret_cast<float4*>(out) + base4;

        const bool has2 = (tid + 512) < V4PB;   // 648 = 256+256+136
        const float4 x0 = __ldcs(&p4[tid]);
        const float4 T0 = __ldcs(&t4[tid]);
        const float4 x1 = __ldcs(&p4[tid + 256]);
        const float4 T1 = __ldcs(&t4[tid + 256]);
        float4 x2, T2;
        if (has2) { x2 = __ldcs(&p4[tid + 512]); T2 = __ldcs(&t4[tid + 512]); }

        const float4 c0 = bce4(x0, T0);
        __stcs(&o4[tid], c0);
        *reinterpret_cast<float4*>(&s_ce[tid * 4]) = c0;
        const float4 c1 = bce4(x1, T1);
        __stcs(&o4[tid + 256], c1);
        *reinterpret_cast<float4*>(&s_ce[(tid + 256) * 4]) = c1;
        if (has2) {
            const float4 c2 = bce4(x2, T2);
            __stcs(&o4[tid + 512], c2);
            *reinterpret_cast<float4*>(&s_ce[(tid + 512) * 4]) = c2;
        }
    }
    __syncthreads();

    // ===================== Phase 2: per-anchor max =====================
    const int gbase = blockIdx.x * APB;
#pragma unroll
    for (int k = 0; k < APB / 8; k++) {
        const int a = wid + k * 8;
        float m = s_ce[a * C + lane];
        if (lane + 32 < C) m = fmaxf(m, s_ce[a * C + lane + 32]);
        if (lane + 64 < C) m = fmaxf(m, s_ce[a * C + lane + 64]);
#pragma unroll
        for (int off = 16; off; off >>= 1)
            m = fmaxf(m, __shfl_xor_sync(FULL, m, off));
        if (lane == 0) s_m[a] = m;              // raw max
    }
    __syncthreads();

    // Warp 0: coalesced depth load, masked max store, ballots.
    if (wid == 0) {
        const int g = gbase + lane;
        const int d = depth[g];
        const float meff = (d != 0) ? 0.0f : s_m[lane];
        g_maxce[g] = meff;                      // coalesced 128B
        const unsigned posb  = __ballot_sync(FULL, d > 0);
        const unsigned zerob = __ballot_sync(FULL, meff == 0.0f);
        if (lane == 0) {
            g_posmask[blockIdx.x]  = posb;
            g_zeromask[blockIdx.x] = zerob;
        }
    }
    __syncthreads();

    // ===================== Ticket: am I the last block of my batch? ====
    if (tid == 0) {
        __threadfence();
        const int t = atomicAdd(&g_done[batch], 1);
        s_flag = (t == BPB - 1);
    }
    __syncthreads();
    if (!s_flag) return;

    const int b = batch;
    if (tid == 0) g_done[b] = 0;                // reset for next replay
    __threadfence();                            // see other blocks' writes

    // ===================== Selection (256 threads, 2 words/thread) =====
    const int w0 = b * WPB + tid * 2;
    const unsigned p0 = g_posmask[w0],  p1 = g_posmask[w0 + 1];
    const unsigned z0 = g_zeromask[w0], z1 = g_zeromask[w0 + 1];
    const int myz  = __popc(z0) + __popc(z1);
    const int pack = myz | ((__popc(p0) + __popc(p1)) << 16);

    // inclusive block scan of pack (zeros in low 16, pos in high 16; no carry)
    int ws = pack;
#pragma unroll
    for (int off = 1; off < 32; off <<= 1) {
        const int n = __shfl_up_sync(FULL, ws, off);
        if (lane >= off) ws += n;
    }
    if (lane == 31) s_scan[wid] = ws;
    __syncthreads();
    if (wid == 0) {
        int y = (lane < 8) ? s_scan[lane] : 0;
        const int orig = y;
#pragma unroll
        for (int off = 1; off < 8; off <<= 1) {
            const int n = __shfl_up_sync(FULL, y, off);
            if (lane >= off) y += n;
        }
        if (lane < 8) s_scan[lane] = y - orig;  // exclusive warp bases
        if (lane == 7) s_bc = y;                // grand total
    }
    __syncthreads();

    const int excl  = s_scan[wid] + (ws - pack);
    const int zbase0 = excl & 0xFFFF;           // zero-rank base (word 2*tid)
    const int total = s_bc;
    const int zeros = total & 0xFFFF;
    const int num_pos = total >> 16;
    const int cgt = A - zeros;                  // count(v > 0)

    const int ratio = npr_ptr ? *npr_ptr : 3;
    int num_neg = ratio * num_pos;
    if (num_neg > A - 1) num_neg = A - 1;
    if (num_neg < 0)     num_neg = 0;

    if (num_neg == 0 || num_neg > cgt) {
        // -------- FAST PATH: v* == 0 (or no negatives) --------
        const bool have_neg = (num_neg > 0);
        const int  r_ties   = have_neg ? (num_neg - cgt) : 0;
#pragma unroll
        for (int k = 0; k < 2; k++) {
            const unsigned zb = k ? z1 : z0;
            const unsigned pb = k ? p1 : p0;
            const int zbase = k ? (zbase0 + __popc(z0)) : zbase0;
            const int abase = (tid * 2 + k) * 32;
#pragma unroll 4
            for (int bit = 0; bit < 32; bit++) {
                const bool zero = (zb >> bit) & 1u;
                const bool pos  = (pb >> bit) & 1u;
                bool neg;
                if (!have_neg)  neg = false;
                else if (!zero) neg = true;     // v > 0 > v*
                else            neg = (zbase + __popc(zb & ((1u << bit) - 1))) < r_ties;
                if (!(pos || neg)) {
                    float* row = out + ((size_t)b * A + abase + bit) * C;
#pragma unroll
                    for (int c = 0; c < C; c++) row[c] = 0.0f;
                }
            }
        }
        return;
    }

    // -------- SLOW PATH (rare): radix select over g_maxce (L2-resident) ----
    const uint32_t* vrow = reinterpret_cast<const uint32_t*>(g_maxce) + (size_t)b * A;

    uint32_t vstar = 0;
    int r_ties = 0;
    {
        uint32_t prefix = 0, pmask = 0;
        int rem = num_neg;
        for (int bit = 30; bit >= 0; bit -= 2) {
            unsigned long long pc = 0;
            for (int k = 0; k < 64; k++) {
                const uint32_t v = vrow[tid * 64 + k];
                if ((v & pmask) == prefix) {
                    const unsigned two = (v >> bit) & 3u;
                    pc += (two == 3u) ? (1ull << 42)
                        : (two == 2u) ? (1ull << 21)
                        : (two == 1u) ? 1ull : 0ull;
                }
            }
#pragma unroll
            for (int off = 16; off; off >>= 1) pc += __shfl_xor_sync(FULL, pc, off);
            if (lane == 0) s_red[wid] = pc;
            __syncthreads();
            if (wid == 0) {
                unsigned long long y = (lane < 8) ? s_red[lane] : 0ull;
#pragma unroll
                for (int off = 4; off; off >>= 1) y += __shfl_xor_sync(FULL, y, off);
                if (lane == 0) s_red[0] = y;
            }
            __syncthreads();
            pc = s_red[0];
            __syncthreads();

            const int c3 = (int)((pc >> 42) & 0x1FFFFF);
            const int c2 = (int)((pc >> 21) & 0x1FFFFF);
            const int c1 = (int)( pc        & 0x1FFFFF);
            uint32_t sel;
            if      (c3 >= rem)           { sel = 3u; }
            else if (c3 + c2 >= rem)      { sel = 2u; rem -= c3; }
            else if (c3 + c2 + c1 >= rem) { sel = 1u; rem -= c3 + c2; }
            else                          { sel = 0u; rem -= c3 + c2 + c1; }
            prefix |= sel << bit;
            pmask  |= 3u << bit;
        }
        vstar  = prefix;
        r_ties = rem;
    }

    // stable tie rank over contiguous ownership [tid*64, tid*64+64)
    int myties = 0;
    for (int k = 0; k < 64; k++) myties += (vrow[tid * 64 + k] == vstar);
    int ts = myties;
#pragma unroll
    for (int off = 1; off < 32; off <<= 1) {
        const int n = __shfl_up_sync(FULL, ts, off);
        if (lane >= off) ts += n;
    }
    if (lane == 31) s_scan[wid] = ts;
    __syncthreads();
    if (wid == 0) {
        int y = (lane < 8) ? s_scan[lane] : 0;
        const int orig = y;
#pragma unroll
        for (int off = 1; off < 8; off <<= 1) {
            const int n = __shfl_up_sync(FULL, y, off);
            if (lane >= off) y += n;
        }
        if (lane < 8) s_scan[lane] = y - orig;
    }
    __syncthreads();
    int tie_idx = s_scan[wid] + (ts - myties);

    for (int k = 0; k < 64; k++) {
        const int a = tid * 64 + k;
        const uint32_t v = vrow[a];
        const bool tie = (v == vstar);
        const bool neg = (v > vstar) || (tie && tie_idx < r_ties);
        if (tie) tie_idx++;
        const unsigned pw = (k < 32) ? p0 : p1;
        const bool pos = (pw >> (a & 31)) & 1u;
        if (!(pos || neg)) {
            float* row = out + ((size_t)b * A + a) * C;
#pragma unroll
            for (int c = 0; c < C; c++) row[c] = 0.0f;
        }
    }
}

// ---------------------------------------------------------------------------
extern "C" void kernel_launch(void* const* d_in, const int* in_sizes, int n_in,
                              void* d_out, int out_size)
{
    const float* pred  = (const float*)d_in[0];
    const float* tgt   = (const float*)d_in[1];
    const int*   depth = (const int*)d_in[2];
    const int*   npr   = (n_in >= 4) ? (const int*)d_in[3] : nullptr;
    float* out = (float*)d_out;

    fused_kernel<<<(B * A) / APB, 256>>>(pred, tgt, depth, npr, out);
}

// round 7
// speedup vs baseline: 1.1454x; 1.1454x over previous
#include <cuda_runtime.h>
#include <cuda_bf16.h>
#include <cstdint>

constexpr int B = 32;
constexpr int A = 16384;
constexpr int C = 81;

constexpr int APB  = 64;            // anchors per ce block
constexpr int FPB  = APB * C;       // 5184 floats
constexpr int V4PB = FPB / 4;       // 1296 float4
constexpr int NT   = 512;           // ce threads per block
constexpr int WPB  = A / 32;        // 512 mask words per batch

// Scratch (device globals; no allocations allowed).
__device__ float    g_maxce[B * A];         // slow path only
__device__ unsigned g_posmask[B * WPB];     // bit: depth > 0
__device__ unsigned g_zeromask[B * WPB];    // bit: v == 0  (v = masked max_ce)

// ---------------------------------------------------------------------------
__device__ __forceinline__ float bce(float x, float t) {
    return fmaxf(x, 0.0f) + log1pf(__expf(-fabsf(x))) - t * x;
}
__device__ __forceinline__ float4 bce4(float4 x, float4 t) {
    float4 r;
    r.x = bce(x.x, t.x); r.y = bce(x.y, t.y);
    r.z = bce(x.z, t.z); r.w = bce(x.w, t.w);
    return r;
}

// ---------------------------------------------------------------------------
// Kernel 1: BCE-with-logits + per-anchor max + per-batch bitmasks.
// 64 anchors/block = 1296 float4 (128B-aligned block ranges), 512 threads.
// Loads front-batched (6 LDG.128 in flight per thread).
// ---------------------------------------------------------------------------
__global__ void __launch_bounds__(NT) ce_kernel(
    const float* __restrict__ pred,
    const float* __restrict__ tgt,
    const int*   __restrict__ depth,
    float*       __restrict__ out)
{
    __shared__ float s_ce[FPB];
    __shared__ float s_m[APB];

    const int tid = threadIdx.x;
    const size_t base4 = (size_t)blockIdx.x * V4PB;
    const float4* __restrict__ p4 = reinterpret_cast<const float4*>(pred) + base4;
    const float4* __restrict__ t4 = reinterpret_cast<const float4*>(tgt)  + base4;
    float4* __restrict__ o4 = reinterpret_cast<float4*>(out) + base4;

    // Front-batched loads: 1296 = 512 + 512 + 272.
    const bool has2 = (tid + 1024) < V4PB;
    const float4 x0 = __ldcs(&p4[tid]);
    const float4 T0 = __ldcs(&t4[tid]);
    const float4 x1 = __ldcs(&p4[tid + 512]);
    const float4 T1 = __ldcs(&t4[tid + 512]);
    float4 x2, T2;
    if (has2) { x2 = __ldcs(&p4[tid + 1024]); T2 = __ldcs(&t4[tid + 1024]); }

    const float4 c0 = bce4(x0, T0);
    __stcs(&o4[tid], c0);
    *reinterpret_cast<float4*>(&s_ce[tid * 4]) = c0;

    const float4 c1 = bce4(x1, T1);
    __stcs(&o4[tid + 512], c1);
    *reinterpret_cast<float4*>(&s_ce[(tid + 512) * 4]) = c1;

    if (has2) {
        const float4 c2 = bce4(x2, T2);
        __stcs(&o4[tid + 1024], c2);
        *reinterpret_cast<float4*>(&s_ce[(tid + 1024) * 4]) = c2;
    }
    __syncthreads();

    const int lane  = tid & 31;
    const int wid   = tid >> 5;            // 0..15
    const int gbase = blockIdx.x * APB;

    // Phase 2: per-anchor max (16 warps x 4 anchors).
#pragma unroll
    for (int k = 0; k < APB / 16; k++) {
        const int a = wid + k * 16;
        float m = s_ce[a * C + lane];
        if (lane + 32 < C) m = fmaxf(m, s_ce[a * C + lane + 32]);
        if (lane + 64 < C) m = fmaxf(m, s_ce[a * C + lane + 64]);
#pragma unroll
        for (int off = 16; off; off >>= 1)
            m = fmaxf(m, __shfl_xor_sync(0xffffffffu, m, off));
        if (lane == 0) s_m[a] = m;
    }
    __syncthreads();

    // Warps 0-1: coalesced depth load, masked max store, ballots.
    if (wid < 2) {
        const int a = wid * 32 + lane;
        const int g = gbase + a;
        const int d = depth[g];
        const float meff = (d != 0) ? 0.0f : s_m[a];
        g_maxce[g] = meff;
        const unsigned posb  = __ballot_sync(0xffffffffu, d > 0);
        const unsigned zerob = __ballot_sync(0xffffffffu, meff == 0.0f);
        if (lane == 0) {
            const int w = blockIdx.x * 2 + wid;   // global anchor-word index
            g_posmask[w]  = posb;
            g_zeromask[w] = zerob;
        }
    }
}

// ---------------------------------------------------------------------------
// Kernel 2: per-batch hard-negative selection + row zeroing. Block per batch.
// Stats computed from the 4 KB/batch bitmasks.
// Fast path (num_neg > cgt): v* = 0; only bitmasks needed.
// Slow path: register radix select over g_maxce (general correctness).
// ---------------------------------------------------------------------------
__global__ void __launch_bounds__(1024) mask_kernel(
    const int* __restrict__ npr_ptr,
    float*     __restrict__ out)
{
    const int b    = blockIdx.x;
    const int tid  = threadIdx.x;
    const int lane = tid & 31;
    const int wid  = tid >> 5;
    const unsigned FULL = 0xffffffffu;

    __shared__ unsigned long long s_red[32];
    __shared__ int s_scan[32];
    __shared__ int s_stats;

    // ---- load bitmasks + stats reduce (num_pos | cgt<<16 packed) ----
    unsigned pb = 0, zb = 0;
    if (tid < WPB) {
        pb = g_posmask[b * WPB + tid];
        zb = g_zeromask[b * WPB + tid];
    }
    {
        int pack = __popc(pb) | ((tid < WPB ? 32 - __popc(zb) : 0) << 16);
#pragma unroll
        for (int off = 16; off; off >>= 1) pack += __shfl_xor_sync(FULL, pack, off);
        if (lane == 0) s_scan[wid] = pack;
        __syncthreads();
        if (wid == 0) {
            int y = s_scan[lane];
#pragma unroll
            for (int off = 16; off; off >>= 1) y += __shfl_xor_sync(FULL, y, off);
            if (lane == 0) s_stats = y;
        }
        __syncthreads();
    }
    const int num_pos = s_stats & 0xFFFF;
    const int cgt     = s_stats >> 16;

    const int ratio = npr_ptr ? *npr_ptr : 3;
    int num_neg = ratio * num_pos;
    if (num_neg > A - 1) num_neg = A - 1;
    if (num_neg < 0)     num_neg = 0;
    __syncthreads();

    if (num_neg == 0 || num_neg > cgt) {
        // ---------------- FAST PATH: vstar == 0 (or no negatives) ----------
        const bool have_neg = (num_neg > 0);
        const int  r_ties   = have_neg ? (num_neg - cgt) : 0;

        const int myz = (tid < WPB) ? __popc(zb) : 0;
        int ws = myz;
#pragma unroll
        for (int off = 1; off < 32; off <<= 1) {
            const int n = __shfl_up_sync(FULL, ws, off);
            if (lane >= off) ws += n;
        }
        if (lane == 31) s_scan[wid] = ws;
        __syncthreads();
        if (wid == 0) {
            const int y = s_scan[lane];
            int z = y;
#pragma unroll
            for (int off = 1; off < 32; off <<= 1) {
                const int n = __shfl_up_sync(FULL, z, off);
                if (lane >= off) z += n;
            }
            s_scan[lane] = z - y;
        }
        __syncthreads();

        if (tid < WPB) {
            const int zbase = s_scan[wid] + (ws - myz);  // exclusive zero-rank base
            const int abase = tid * 32;
#pragma unroll 4
            for (int bit = 0; bit < 32; bit++) {
                const bool zero = (zb >> bit) & 1u;
                const bool pos  = (pb >> bit) & 1u;
                bool neg;
                if (!have_neg)   neg = false;
                else if (!zero)  neg = true;             // v > 0 > vstar
                else             neg = (zbase + __popc(zb & ((1u << bit) - 1))) < r_ties;
                if (!(pos || neg)) {
                    float* row = out + ((size_t)b * A + abase + bit) * C;
#pragma unroll
                    for (int c = 0; c < C; c++) row[c] = 0.0f;
                }
            }
        }
        return;
    }

    // ---------------- SLOW PATH: general radix select (0 < num_neg <= cgt) --
    const uint32_t* vrow = reinterpret_cast<const uint32_t*>(g_maxce) + (size_t)b * A;

    uint32_t v[16];
    const uint4* vv = reinterpret_cast<const uint4*>(vrow) + tid * 4;
#pragma unroll
    for (int q = 0; q < 4; q++) {
        const uint4 u = vv[q];
        v[q * 4 + 0] = u.x; v[q * 4 + 1] = u.y; v[q * 4 + 2] = u.z; v[q * 4 + 3] = u.w;
    }
    unsigned pmaskbits;
    {
        const unsigned pw = g_posmask[b * WPB + (tid >> 1)];
        pmaskbits = (pw >> ((tid & 1) * 16)) & 0xFFFFu;
    }

    uint32_t vstar = 0;
    int r_ties = 0;
    {
        uint32_t prefix = 0, pmask = 0;
        int rem = num_neg;
#pragma unroll
        for (int bit = 30; bit >= 0; bit -= 2) {
            unsigned long long pc = 0;
#pragma unroll
            for (int j = 0; j < 16; j++) {
                if ((v[j] & pmask) == prefix) {
                    const unsigned two = (v[j] >> bit) & 3u;
                    pc += (two == 3u) ? (1ull << 42)
                        : (two == 2u) ? (1ull << 21)
                        : (two == 1u) ? 1ull : 0ull;
                }
            }
#pragma unroll
            for (int off = 16; off; off >>= 1) pc += __shfl_xor_sync(FULL, pc, off);
            if (lane == 0) s_red[wid] = pc;
            __syncthreads();
            if (wid == 0) {
                unsigned long long y = s_red[lane];
#pragma unroll
                for (int off = 16; off; off >>= 1) y += __shfl_xor_sync(FULL, y, off);
                if (lane == 0) s_red[0] = y;
            }
            __syncthreads();
            pc = s_red[0];
            __syncthreads();

            const int c3 = (int)((pc >> 42) & 0x1FFFFF);
            const int c2 = (int)((pc >> 21) & 0x1FFFFF);
            const int c1 = (int)( pc        & 0x1FFFFF);
            uint32_t sel;
            if      (c3 >= rem)           { sel = 3u; }
            else if (c3 + c2 >= rem)      { sel = 2u; rem -= c3; }
            else if (c3 + c2 + c1 >= rem) { sel = 1u; rem -= c3 + c2; }
            else                          { sel = 0u; rem -= c3 + c2 + c1; }
            prefix |= sel << bit;
            pmask  |= 3u << bit;
        }
        vstar  = prefix;
        r_ties = rem;
    }

    int myties = 0;
#pragma unroll
    for (int j = 0; j < 16; j++) myties += (v[j] == vstar);
    int ws = myties;
#pragma unroll
    for (int off = 1; off < 32; off <<= 1) {
        const int n = __shfl_up_sync(FULL, ws, off);
        if (lane >= off) ws += n;
    }
    if (lane == 31) s_scan[wid] = ws;
    __syncthreads();
    if (wid == 0) {
        const int y = s_scan[lane];
        int z = y;
#pragma unroll
        for (int off = 1; off < 32; off <<= 1) {
            const int n = __shfl_up_sync(FULL, z, off);
            if (lane >= off) z += n;
        }
        s_scan[lane] = z - y;
    }
    __syncthreads();
    int tie_idx = s_scan[wid] + (ws - myties);

    const int abase = tid * 16;
#pragma unroll
    for (int j = 0; j < 16; j++) {
        const bool tie = (v[j] == vstar);
        const bool neg = (v[j] > vstar) || (tie && tie_idx < r_ties);
        if (tie) tie_idx++;
        const bool keep = ((pmaskbits >> j) & 1u) || neg;
        if (!keep) {
            float* row = out + ((size_t)b * A + abase + j) * C;
#pragma unroll
            for (int c = 0; c < C; c++) row[c] = 0.0f;
        }
    }
}

// ---------------------------------------------------------------------------
extern "C" void kernel_launch(void* const* d_in, const int* in_sizes, int n_in,
                              void* d_out, int out_size)
{
    const float* pred  = (const float*)d_in[0];
    const float* tgt   = (const float*)d_in[1];
    const int*   depth = (const int*)d_in[2];
    const int*   npr   = (n_in >= 4) ? (const int*)d_in[3] : nullptr;
    float* out = (float*)d_out;

    ce_kernel<<<(B * A) / APB, NT>>>(pred, tgt, depth, out);
    mask_kernel<<<B, 1024>>>(npr, out);
}

// round 9
// speedup vs baseline: 1.3619x; 1.1891x over previous
#include <cuda_runtime.h>
#include <cuda_bf16.h>
#include <cstdint>

constexpr int B = 32;
constexpr int A = 16384;
constexpr int C = 81;

constexpr int APB  = 32;            // anchors per ce block
constexpr int FPB  = APB * C;       // 2592 floats
constexpr int V4PB = FPB / 4;       // 648 float4
constexpr int WPB  = A / 32;        // 512 mask words per batch

// Scratch (device globals; no allocations allowed).
__device__ float    g_maxce[B * A];         // slow path only
__device__ unsigned g_posmask[B * WPB];     // bit: depth > 0
__device__ unsigned g_zeromask[B * WPB];    // bit: v == 0  (v = masked max_ce)

// ---------------------------------------------------------------------------
// Raw MUFU helpers (2 ulp approx — fine for 1e-3 tolerance).
// ---------------------------------------------------------------------------
__device__ __forceinline__ float ex2f(float x) {
    float r;
    asm("ex2.approx.f32 %0, %1;" : "=f"(r) : "f"(x));
    return r;
}
__device__ __forceinline__ float lg2f(float x) {
    float r;
    asm("lg2.approx.f32 %0, %1;" : "=f"(r) : "f"(x));
    return r;
}

// Cheap softplus: softplus(x) = max(x,0) + ln2 * log2(1 + 2^(-|x|*log2e)).
// 2 MUFU + ~4 FMA per element; abs error <= ~1e-7.
__device__ __forceinline__ float bce(float x, float t) {
    const float LOG2E = 1.4426950408889634f;
    const float LN2   = 0.6931471805599453f;
    const float e  = ex2f(-LOG2E * fabsf(x));
    const float sp = fmaxf(x, 0.0f) + LN2 * lg2f(1.0f + e);
    return sp - t * x;
}
__device__ __forceinline__ float4 bce4(float4 x, float4 t) {
    float4 r;
    r.x = bce(x.x, t.x); r.y = bce(x.y, t.y);
    r.z = bce(x.z, t.z); r.w = bce(x.w, t.w);
    return r;
}

// ---------------------------------------------------------------------------
// Kernel 1: BCE-with-logits + per-anchor max + per-batch bitmasks.
// 32 anchors/block = 648 float4 (128B-aligned block ranges). Loads are
// front-batched (up to 6 LDG.128 in flight) to maximize DRAM MLP.
// ---------------------------------------------------------------------------
__global__ void __launch_bounds__(256) ce_kernel(
    const float* __restrict__ pred,
    const float* __restrict__ tgt,
    const int*   __restrict__ depth,
    float*       __restrict__ out)
{
    __shared__ float s_ce[FPB];
    __shared__ float s_m[APB];

    const int tid = threadIdx.x;
    const size_t base4 = (size_t)blockIdx.x * V4PB;
    const float4* __restrict__ p4 = reinterpret_cast<const float4*>(pred) + base4;
    const float4* __restrict__ t4 = reinterpret_cast<const float4*>(tgt)  + base4;
    float4* __restrict__ o4 = reinterpret_cast<float4*>(out) + base4;

    // Front-batched loads: 648 = 256 + 256 + 136.
    const bool has2 = (tid + 512) < V4PB;
    const float4 x0 = __ldcs(&p4[tid]);
    const float4 T0 = __ldcs(&t4[tid]);
    const float4 x1 = __ldcs(&p4[tid + 256]);
    const float4 T1 = __ldcs(&t4[tid + 256]);
    float4 x2, T2;
    if (has2) { x2 = __ldcs(&p4[tid + 512]); T2 = __ldcs(&t4[tid + 512]); }

    const float4 c0 = bce4(x0, T0);
    __stcs(&o4[tid], c0);
    *reinterpret_cast<float4*>(&s_ce[tid * 4]) = c0;

    const float4 c1 = bce4(x1, T1);
    __stcs(&o4[tid + 256], c1);
    *reinterpret_cast<float4*>(&s_ce[(tid + 256) * 4]) = c1;

    if (has2) {
        const float4 c2 = bce4(x2, T2);
        __stcs(&o4[tid + 512], c2);
        *reinterpret_cast<float4*>(&s_ce[(tid + 512) * 4]) = c2;
    }
    __syncthreads();

    const int lane  = tid & 31;
    const int wid   = tid >> 5;
    const int gbase = blockIdx.x * APB;

#pragma unroll
    for (int k = 0; k < APB / 8; k++) {
        const int a = wid + k * 8;
        float m = s_ce[a * C + lane];
        if (lane + 32 < C) m = fmaxf(m, s_ce[a * C + lane + 32]);
        if (lane + 64 < C) m = fmaxf(m, s_ce[a * C + lane + 64]);
#pragma unroll
        for (int off = 16; off; off >>= 1)
            m = fmaxf(m, __shfl_xor_sync(0xffffffffu, m, off));
        if (lane == 0) s_m[a] = m;
    }
    __syncthreads();

    // Warp 0: coalesced depth load, masked max store, ballots.
    if (wid == 0) {
        const int g = gbase + lane;
        const int d = depth[g];
        const float meff = (d != 0) ? 0.0f : s_m[lane];
        g_maxce[g] = meff;
        const unsigned posb  = __ballot_sync(0xffffffffu, d > 0);
        const unsigned zerob = __ballot_sync(0xffffffffu, meff == 0.0f);
        if (lane == 0) {
            g_posmask[blockIdx.x]  = posb;
            g_zeromask[blockIdx.x] = zerob;
        }
    }
}

// ---------------------------------------------------------------------------
// Kernel 2: per-batch hard-negative selection + row zeroing. Block per batch.
// Fast path (num_neg > cgt): v* = 0; only bitmasks needed.
// Slow path: register radix select over g_maxce (general correctness).
// ---------------------------------------------------------------------------
__global__ void __launch_bounds__(1024) mask_kernel(
    const int* __restrict__ npr_ptr,
    float*     __restrict__ out)
{
    const int b    = blockIdx.x;
    const int tid  = threadIdx.x;
    const int lane = tid & 31;
    const int wid  = tid >> 5;
    const unsigned FULL = 0xffffffffu;

    __shared__ unsigned long long s_red[32];
    __shared__ int s_scan[32];
    __shared__ int s_stats;

    // ---- load bitmasks + stats reduce (num_pos | cgt<<16 packed) ----
    unsigned pb = 0, zb = 0;
    if (tid < WPB) {
        pb = g_posmask[b * WPB + tid];
        zb = g_zeromask[b * WPB + tid];
    }
    {
        int pack = __popc(pb) | ((tid < WPB ? 32 - __popc(zb) : 0) << 16);
#pragma unroll
        for (int off = 16; off; off >>= 1) pack += __shfl_xor_sync(FULL, pack, off);
        if (lane == 0) s_scan[wid] = pack;
        __syncthreads();
        if (wid == 0) {
            int y = s_scan[lane];
#pragma unroll
            for (int off = 16; off; off >>= 1) y += __shfl_xor_sync(FULL, y, off);
            if (lane == 0) s_stats = y;
        }
        __syncthreads();
    }
    const int num_pos = s_stats & 0xFFFF;
    const int cgt     = s_stats >> 16;

    const int ratio = npr_ptr ? *npr_ptr : 3;
    int num_neg = ratio * num_pos;
    if (num_neg > A - 1) num_neg = A - 1;
    if (num_neg < 0)     num_neg = 0;
    __syncthreads();

    if (num_neg == 0 || num_neg > cgt) {
        // ---------------- FAST PATH: vstar == 0 (or no negatives) ----------
        const bool have_neg = (num_neg > 0);
        const int  r_ties   = have_neg ? (num_neg - cgt) : 0;

        const int myz = (tid < WPB) ? __popc(zb) : 0;
        int ws = myz;
#pragma unroll
        for (int off = 1; off < 32; off <<= 1) {
            const int n = __shfl_up_sync(FULL, ws, off);
            if (lane >= off) ws += n;
        }
        if (lane == 31) s_scan[wid] = ws;
        __syncthreads();
        if (wid == 0) {
            const int y = s_scan[lane];
            int z = y;
#pragma unroll
            for (int off = 1; off < 32; off <<= 1) {
                const int n = __shfl_up_sync(FULL, z, off);
                if (lane >= off) z += n;
            }
            s_scan[lane] = z - y;
        }
        __syncthreads();

        if (tid < WPB) {
            const int zbase = s_scan[wid] + (ws - myz);  // exclusive zero-rank base
            const int abase = tid * 32;
#pragma unroll 4
            for (int bit = 0; bit < 32; bit++) {
                const bool zero = (zb >> bit) & 1u;
                const bool pos  = (pb >> bit) & 1u;
                bool neg;
                if (!have_neg)   neg = false;
                else if (!zero)  neg = true;             // v > 0 > vstar
                else             neg = (zbase + __popc(zb & ((1u << bit) - 1))) < r_ties;
                if (!(pos || neg)) {
                    float* row = out + ((size_t)b * A + abase + bit) * C;
#pragma unroll
                    for (int c = 0; c < C; c++) row[c] = 0.0f;
                }
            }
        }
        return;
    }

    // ---------------- SLOW PATH: general radix select (0 < num_neg <= cgt) --
    const uint32_t* vrow = reinterpret_cast<const uint32_t*>(g_maxce) + (size_t)b * A;

    uint32_t v[16];
    const uint4* vv = reinterpret_cast<const uint4*>(vrow) + tid * 4;
#pragma unroll
    for (int q = 0; q < 4; q++) {
        const uint4 u = vv[q];
        v[q * 4 + 0] = u.x; v[q * 4 + 1] = u.y; v[q * 4 + 2] = u.z; v[q * 4 + 3] = u.w;
    }
    unsigned pmaskbits;
    {
        const unsigned pw = g_posmask[b * WPB + (tid >> 1)];
        pmaskbits = (pw >> ((tid & 1) * 16)) & 0xFFFFu;
    }

    uint32_t vstar = 0;
    int r_ties = 0;
    {
        uint32_t prefix = 0, pmask = 0;
        int rem = num_neg;
#pragma unroll
        for (int bit = 30; bit >= 0; bit -= 2) {
            unsigned long long pc = 0;
#pragma unroll
            for (int j = 0; j < 16; j++) {
                if ((v[j] & pmask) == prefix) {
                    const unsigned two = (v[j] >> bit) & 3u;
                    pc += (two == 3u) ? (1ull << 42)
                        : (two == 2u) ? (1ull << 21)
                        : (two == 1u) ? 1ull : 0ull;
                }
            }
#pragma unroll
            for (int off = 16; off; off >>= 1) pc += __shfl_xor_sync(FULL, pc, off);
            if (lane == 0) s_red[wid] = pc;
            __syncthreads();
            if (wid == 0) {
                unsigned long long y = s_red[lane];
#pragma unroll
                for (int off = 16; off; off >>= 1) y += __shfl_xor_sync(FULL, y, off);
                if (lane == 0) s_red[0] = y;
            }
            __syncthreads();
            pc = s_red[0];
            __syncthreads();

            const int c3 = (int)((pc >> 42) & 0x1FFFFF);
            const int c2 = (int)((pc >> 21) & 0x1FFFFF);
            const int c1 = (int)( pc        & 0x1FFFFF);
            uint32_t sel;
            if      (c3 >= rem)           { sel = 3u; }
            else if (c3 + c2 >= rem)      { sel = 2u; rem -= c3; }
            else if (c3 + c2 + c1 >= rem) { sel = 1u; rem -= c3 + c2; }
            else                          { sel = 0u; rem -= c3 + c2 + c1; }
            prefix |= sel << bit;
            pmask  |= 3u << bit;
        }
        vstar  = prefix;
        r_ties = rem;
    }

    int myties = 0;
#pragma unroll
    for (int j = 0; j < 16; j++) myties += (v[j] == vstar);
    int ws = myties;
#pragma unroll
    for (int off = 1; off < 32; off <<= 1) {
        const int n = __shfl_up_sync(FULL, ws, off);
        if (lane >= off) ws += n;
    }
    if (lane == 31) s_scan[wid] = ws;
    __syncthreads();
    if (wid == 0) {
        const int y = s_scan[lane];
        int z = y;
#pragma unroll
        for (int off = 1; off < 32; off <<= 1) {
            const int n = __shfl_up_sync(FULL, z, off);
            if (lane >= off) z += n;
        }
        s_scan[lane] = z - y;
    }
    __syncthreads();
    int tie_idx = s_scan[wid] + (ws - myties);

    const int abase = tid * 16;
#pragma unroll
    for (int j = 0; j < 16; j++) {
        const bool tie = (v[j] == vstar);
        const bool neg = (v[j] > vstar) || (tie && tie_idx < r_ties);
        if (tie) tie_idx++;
        const bool keep = ((pmaskbits >> j) & 1u) || neg;
        if (!keep) {
            float* row = out + ((size_t)b * A + abase + j) * C;
#pragma unroll
            for (int c = 0; c < C; c++) row[c] = 0.0f;
        }
    }
}

// ---------------------------------------------------------------------------
extern "C" void kernel_launch(void* const* d_in, const int* in_sizes, int n_in,
                              void* d_out, int out_size)
{
    const float* pred  = (const float*)d_in[0];
    const float* tgt   = (const float*)d_in[1];
    const int*   depth = (const int*)d_in[2];
    const int*   npr   = (n_in >= 4) ? (const int*)d_in[3] : nullptr;
    float* out = (float*)d_out;

    ce_kernel<<<(B * A) / APB, 256>>>(pred, tgt, depth, out);
    mask_kernel<<<B, 1024>>>(npr, out);
}

// round 10
// speedup vs baseline: 1.3747x; 1.0094x over previous
#include <cuda_runtime.h>
#include <cuda_bf16.h>
#include <cstdint>

constexpr int B = 32;
constexpr int A = 16384;
constexpr int C = 81;

constexpr int APB  = 32;            // anchors per ce block
constexpr int FPB  = APB * C;       // 2592 floats
constexpr int V4PB = FPB / 4;       // 648 float4
constexpr int WPB  = A / 32;        // 512 mask words per batch

// Scratch (device globals; no allocations allowed).
__device__ float    g_maxce[B * A];         // slow path only
__device__ unsigned g_posmask[B * WPB];     // bit: depth > 0
__device__ unsigned g_zeromask[B * WPB];    // bit: v == 0  (v = masked max_ce)

// ---------------------------------------------------------------------------
// Raw MUFU helpers (2 ulp approx — fine for 1e-3 tolerance).
// ---------------------------------------------------------------------------
__device__ __forceinline__ float ex2f(float x) {
    float r;
    asm("ex2.approx.f32 %0, %1;" : "=f"(r) : "f"(x));
    return r;
}
__device__ __forceinline__ float lg2f(float x) {
    float r;
    asm("lg2.approx.f32 %0, %1;" : "=f"(r) : "f"(x));
    return r;
}

// Cheap softplus: softplus(x) = max(x,0) + ln2 * log2(1 + 2^(-|x|*log2e)).
__device__ __forceinline__ float bce(float x, float t) {
    const float LOG2E = 1.4426950408889634f;
    const float LN2   = 0.6931471805599453f;
    const float e  = ex2f(-LOG2E * fabsf(x));
    const float sp = fmaxf(x, 0.0f) + LN2 * lg2f(1.0f + e);
    return sp - t * x;
}
__device__ __forceinline__ float4 bce4(float4 x, float4 t) {
    float4 r;
    r.x = bce(x.x, t.x); r.y = bce(x.y, t.y);
    r.z = bce(x.z, t.z); r.w = bce(x.w, t.w);
    return r;
}

// ---------------------------------------------------------------------------
// Kernel 1: BCE-with-logits + per-anchor max + per-batch bitmasks.
// ---------------------------------------------------------------------------
__global__ void __launch_bounds__(256) ce_kernel(
    const float* __restrict__ pred,
    const float* __restrict__ tgt,
    const int*   __restrict__ depth,
    float*       __restrict__ out)
{
    __shared__ float s_ce[FPB];
    __shared__ float s_m[APB];

    const int tid = threadIdx.x;
    const size_t base4 = (size_t)blockIdx.x * V4PB;
    const float4* __restrict__ p4 = reinterpret_cast<const float4*>(pred) + base4;
    const float4* __restrict__ t4 = reinterpret_cast<const float4*>(tgt)  + base4;
    float4* __restrict__ o4 = reinterpret_cast<float4*>(out) + base4;

    // Front-batched loads: 648 = 256 + 256 + 136.
    const bool has2 = (tid + 512) < V4PB;
    const float4 x0 = __ldcs(&p4[tid]);
    const float4 T0 = __ldcs(&t4[tid]);
    const float4 x1 = __ldcs(&p4[tid + 256]);
    const float4 T1 = __ldcs(&t4[tid + 256]);
    float4 x2, T2;
    if (has2) { x2 = __ldcs(&p4[tid + 512]); T2 = __ldcs(&t4[tid + 512]); }

    const float4 c0 = bce4(x0, T0);
    __stcs(&o4[tid], c0);
    *reinterpret_cast<float4*>(&s_ce[tid * 4]) = c0;

    const float4 c1 = bce4(x1, T1);
    __stcs(&o4[tid + 256], c1);
    *reinterpret_cast<float4*>(&s_ce[(tid + 256) * 4]) = c1;

    if (has2) {
        const float4 c2 = bce4(x2, T2);
        __stcs(&o4[tid + 512], c2);
        *reinterpret_cast<float4*>(&s_ce[(tid + 512) * 4]) = c2;
    }
    __syncthreads();

    const int lane  = tid & 31;
    const int wid   = tid >> 5;
    const int gbase = blockIdx.x * APB;

#pragma unroll
    for (int k = 0; k < APB / 8; k++) {
        const int a = wid + k * 8;
        float m = s_ce[a * C + lane];
        if (lane + 32 < C) m = fmaxf(m, s_ce[a * C + lane + 32]);
        if (lane + 64 < C) m = fmaxf(m, s_ce[a * C + lane + 64]);
#pragma unroll
        for (int off = 16; off; off >>= 1)
            m = fmaxf(m, __shfl_xor_sync(0xffffffffu, m, off));
        if (lane == 0) s_m[a] = m;
    }
    __syncthreads();

    // Warp 0: coalesced depth load, masked max store, ballots.
    if (wid == 0) {
        const int g = gbase + lane;
        const int d = depth[g];
        const float meff = (d != 0) ? 0.0f : s_m[lane];
        g_maxce[g] = meff;
        const unsigned posb  = __ballot_sync(0xffffffffu, d > 0);
        const unsigned zerob = __ballot_sync(0xffffffffu, meff == 0.0f);
        if (lane == 0) {
            g_posmask[blockIdx.x]  = posb;
            g_zeromask[blockIdx.x] = zerob;
        }
    }

#if __CUDA_ARCH__ >= 900
    cudaTriggerProgrammaticLaunchCompletion();
#endif
}

// ---------------------------------------------------------------------------
// Kernel 2: per-batch hard-negative selection + row zeroing.
// 512 threads / batch, 1 bitmask word per thread. ONE packed scan yields
// num_pos, cgt, and per-word zero-rank bases simultaneously.
// ---------------------------------------------------------------------------
__global__ void __launch_bounds__(512) mask_kernel(
    const int* __restrict__ npr_ptr,
    float*     __restrict__ out)
{
#if __CUDA_ARCH__ >= 900
    cudaGridDependencySynchronize();
#endif
    const int b    = blockIdx.x;
    const int tid  = threadIdx.x;
    const int lane = tid & 31;
    const int wid  = tid >> 4 >> 1;        // tid >> 5, 0..15
    const unsigned FULL = 0xffffffffu;

    __shared__ unsigned long long s_red[16];
    __shared__ int s_w[16];
    __shared__ int s_scan[16];
    __shared__ int s_total;

    // ---- load my word of each bitmask ----
    const unsigned pb = g_posmask[b * WPB + tid];
    const unsigned zb = g_zeromask[b * WPB + tid];

    // ---- single packed inclusive scan: zeros | num_pos<<16 ----
    const int pack = __popc(zb) | (__popc(pb) << 16);
    int inc = pack;
#pragma unroll
    for (int off = 1; off < 32; off <<= 1) {
        const int n = __shfl_up_sync(FULL, inc, off);
        if (lane >= off) inc += n;
    }
    if (lane == 31) s_w[wid] = inc;
    __syncthreads();
    if (wid == 0 && lane < 16) {
        const int y = s_w[lane];
        int z = y;
#pragma unroll
        for (int off = 1; off < 16; off <<= 1) {
            const int n = __shfl_up_sync(0xFFFFu, z, off);
            if (lane >= off) z += n;
        }
        s_scan[lane] = z - y;              // exclusive warp bases
        if (lane == 15) s_total = z;       // grand total
    }
    __syncthreads();

    const int excl  = s_scan[wid] + (inc - pack);
    const int zbase = excl & 0xFFFF;       // zeros strictly before my word
    const int total = s_total;
    const int zeros = total & 0xFFFF;
    const int num_pos = total >> 16;
    const int cgt     = A - zeros;         // count(v > 0)

    const int ratio = npr_ptr ? *npr_ptr : 3;
    int num_neg = ratio * num_pos;
    if (num_neg > A - 1) num_neg = A - 1;
    if (num_neg < 0)     num_neg = 0;

    if (num_neg == 0 || num_neg > cgt) {
        // ---------------- FAST PATH: vstar == 0 (or no negatives) ----------
        const bool have_neg = (num_neg > 0);
        const int  r_ties   = have_neg ? (num_neg - cgt) : 0;
        const int  abase    = tid * 32;
#pragma unroll 4
        for (int bit = 0; bit < 32; bit++) {
            const bool zero = (zb >> bit) & 1u;
            const bool pos  = (pb >> bit) & 1u;
            bool neg;
            if (!have_neg)   neg = false;
            else if (!zero)  neg = true;   // v > 0 > vstar
            else             neg = (zbase + __popc(zb & ((1u << bit) - 1))) < r_ties;
            if (!(pos || neg)) {
                float* row = out + ((size_t)b * A + abase + bit) * C;
#pragma unroll
                for (int c = 0; c < C; c++) row[c] = 0.0f;
            }
        }
        return;
    }

    // ---------------- SLOW PATH: general radix select (0 < num_neg <= cgt) --
    const uint32_t* vrow = reinterpret_cast<const uint32_t*>(g_maxce) + (size_t)b * A;

    uint32_t v[32];
    const uint4* vv = reinterpret_cast<const uint4*>(vrow) + tid * 8;
#pragma unroll
    for (int q = 0; q < 8; q++) {
        const uint4 u = vv[q];
        v[q * 4 + 0] = u.x; v[q * 4 + 1] = u.y; v[q * 4 + 2] = u.z; v[q * 4 + 3] = u.w;
    }

    uint32_t vstar = 0;
    int r_ties = 0;
    {
        uint32_t prefix = 0, pmask = 0;
        int rem = num_neg;
#pragma unroll
        for (int bit = 30; bit >= 0; bit -= 2) {
            unsigned long long pc = 0;
#pragma unroll
            for (int j = 0; j < 32; j++) {
                if ((v[j] & pmask) == prefix) {
                    const unsigned two = (v[j] >> bit) & 3u;
                    pc += (two == 3u) ? (1ull << 42)
                        : (two == 2u) ? (1ull << 21)
                        : (two == 1u) ? 1ull : 0ull;
                }
            }
#pragma unroll
            for (int off = 16; off; off >>= 1) pc += __shfl_xor_sync(FULL, pc, off);
            if (lane == 0) s_red[wid] = pc;
            __syncthreads();
            if (wid == 0 && lane < 16) {
                unsigned long long y = s_red[lane];
#pragma unroll
                for (int off = 8; off; off >>= 1) y += __shfl_xor_sync(0xFFFFu, y, off);
                if (lane == 0) s_red[0] = y;
            }
            __syncthreads();
            pc = s_red[0];
            __syncthreads();

            const int c3 = (int)((pc >> 42) & 0x1FFFFF);
            const int c2 = (int)((pc >> 21) & 0x1FFFFF);
            const int c1 = (int)( pc        & 0x1FFFFF);
            uint32_t sel;
            if      (c3 >= rem)           { sel = 3u; }
            else if (c3 + c2 >= rem)      { sel = 2u; rem -= c3; }
            else if (c3 + c2 + c1 >= rem) { sel = 1u; rem -= c3 + c2; }
            else                          { sel = 0u; rem -= c3 + c2 + c1; }
            prefix |= sel << bit;
            pmask  |= 3u << bit;
        }
        vstar  = prefix;
        r_ties = rem;
    }

    // stable tie rank: exclusive block scan of per-thread tie counts
    int myties = 0;
#pragma unroll
    for (int j = 0; j < 32; j++) myties += (v[j] == vstar);
    int ws = myties;
#pragma unroll
    for (int off = 1; off < 32; off <<= 1) {
        const int n = __shfl_up_sync(FULL, ws, off);
        if (lane >= off) ws += n;
    }
    if (lane == 31) s_w[wid] = ws;
    __syncthreads();
    if (wid == 0 && lane < 16) {
        const int y = s_w[lane];
        int z = y;
#pragma unroll
        for (int off = 1; off < 16; off <<= 1) {
            const int n = __shfl_up_sync(0xFFFFu, z, off);
            if (lane >= off) z += n;
        }
        s_scan[lane] = z - y;
    }
    __syncthreads();
    int tie_idx = s_scan[wid] + (ws - myties);

    const int abase = tid * 32;
#pragma unroll
    for (int j = 0; j < 32; j++) {
        const bool tie = (v[j] == vstar);
        const bool neg = (v[j] > vstar) || (tie && tie_idx < r_ties);
        if (tie) tie_idx++;
        const bool keep = ((pb >> j) & 1u) || neg;
        if (!keep) {
            float* row = out + ((size_t)b * A + abase + j) * C;
#pragma unroll
            for (int c = 0; c < C; c++) row[c] = 0.0f;
        }
    }
}

// ---------------------------------------------------------------------------
extern "C" void kernel_launch(void* const* d_in, const int* in_sizes, int n_in,
                              void* d_out, int out_size)
{
    const float* pred  = (const float*)d_in[0];
    const float* tgt   = (const float*)d_in[1];
    const int*   depth = (const int*)d_in[2];
    const int*   npr   = (n_in >= 4) ? (const int*)d_in[3] : nullptr;
    float* out = (float*)d_out;

    ce_kernel<<<(B * A) / APB, 256>>>(pred, tgt, depth, out);

    // Programmatic dependent launch: mask waits in-kernel via
    // cudaGridDependencySynchronize(); launch overlaps ce's tail.
    cudaLaunchAttribute attrs[1];
    attrs[0].id = cudaLaunchAttributeProgrammaticStreamSerialization;
    attrs[0].val.programmaticStreamSerializationAllowed = 1;
    cudaLaunchConfig_t cfg = {};
    cfg.gridDim  = dim3(B, 1, 1);
    cfg.blockDim = dim3(512, 1, 1);
    cfg.dynamicSmemBytes = 0;
    cfg.stream = 0;
    cfg.attrs = attrs;
    cfg.numAttrs = 1;
    cudaLaunchKernelEx(&cfg, mask_kernel, npr, out);
}